// round 10
// baseline (speedup 1.0000x reference)
#include <cuda_runtime.h>
#include <math.h>

// F0Resonance: out[b,e,s] = normalize_s( sum_o w_o * sin(phase_o[s]) )
//
// Numerics model H4 (VALIDATED R7/R8/R9, rel_err 2.35e-7): cumsum -> reduce_window;
// XLA ReduceWindowRewriter (base_length=16) recursive decomposition
// 32768 -> 2048 -> 128 -> 8. For 0-based sample s, g=s>>4, r=s&15:
//   phase(s) = fl(EB(g) + LA[r]);  EB(g) = 0 if g==0 else fl(ECt[(g-1)>>4] + LB[(g-1)&15])
// Octave-axis cumsums (N=16): naive sequential folds. theta: separate mul/add.
// The PHASE rounding chain is bit-matched to the reference — do not alter it.
// (Amplitude path may use FMA: only ~ulp-level effect on output.)

#define NSAMP  32768
#define NOCT   16
#define NEV    256            // B*E = 4*64
#define K1T    512            // 16 warps; each warp owns 256 samples
#define QY     8              // 8 * 16 warps * 256 samples = 32768
#define GPB    256            // g-groups per block (16 warps * 16)
#define K2T    256

__device__ float g_partmax[NEV * QY];

__global__ void __launch_bounds__(K1T, 2)   // 64-reg budget: NO spills (R9 capped
                                            // at 32 regs and spilled -> stalls)
f0res_main(const float* __restrict__ f0_in,
           const float* __restrict__ dc_in,
           const float* __restrict__ fs_in,
           float* __restrict__ out) {
    const int ev   = blockIdx.x;          // 0..255
    const int q    = blockIdx.y;          // 0..7
    const int tid  = threadIdx.x;
    const int warp = tid >> 5;
    const int lane = tid & 31;

    __shared__ float sh_LA[NOCT][16];
    __shared__ float sh_LB[NOCT][16];
    __shared__ float sh_LC[NOCT][16];
    __shared__ float sh_SD[NOCT][8];
    __shared__ float sh_ECt[NOCT][128];    // EC(i): 0 if i==0 else SC[i-1]
    __shared__ float sh_EB[NOCT][GPB];     // EB(g) for this block's 256 groups
    __shared__ float sh_w[NOCT];
    __shared__ float sh_wmax[K1T / 32];

    // ---- Prolog A: per-octave theta, weight, scan tables (threads 0..15) ----
    if (tid < NOCT) {
        const int o = tid;
        const int n = o + 1;
        const float MIN_FREQ_F   = (float)(20.0 / 11025.0);
        const float FREQ_RANGE_F = (float)(3000.0 / 11025.0 - 20.0 / 11025.0);
        const float PI_F = 3.14159265358979323846f;

        float f0 = fabsf(f0_in[ev]);
        float f0a = __fmul_rn(__fadd_rn(MIN_FREQ_F, __fmul_rn(f0, FREQ_RANGE_F)), PI_F);

        float fs = fs_in[ev];
        float fac = fs;
        for (int i = 1; i < n; i++) fac = __fadd_rn(fac, fs);
        const float th = __fmul_rn(f0a, fac);

        float dc = dc_in[ev];
        float s1 = 1.0f / (1.0f + expf(-dc));
        float s2 = 1.0f / (1.0f + expf(-s1));
        float decay = __fadd_rn(0.01f, __fmul_rn(s2, (float)((1.0 - 0.01) * 0.95)));
        float ld = logf(__fadd_rn(decay, 1e-12f));
        float cum = ld;
        for (int i = 1; i < n; i++) cum = __fadd_rn(cum, ld);
        sh_w[o] = expf(cum);

        float acc = 0.f;
        for (int r = 0; r < 16; r++) { acc = __fadd_rn(acc, th); sh_LA[o][r] = acc; }
        const float TA = acc;
        acc = 0.f;
        for (int r = 0; r < 16; r++) { acc = __fadd_rn(acc, TA); sh_LB[o][r] = acc; }
        const float TB = acc;
        acc = 0.f;
        for (int r = 0; r < 16; r++) { acc = __fadd_rn(acc, TB); sh_LC[o][r] = acc; }
        const float TC = acc;
        acc = 0.f;
        for (int j = 0; j < 8; j++) { acc = __fadd_rn(acc, TC); sh_SD[o][j] = acc; }

        sh_ECt[o][0] = 0.f;
        for (int m = 0; m < 127; m++) {
            const int i3 = m >> 4, r3 = m & 15;
            float ED = (i3 == 0) ? 0.f : sh_SD[o][i3 - 1];
            sh_ECt[o][m + 1] = __fadd_rn(ED, sh_LC[o][r3]);
        }
    }
    __syncthreads();

    // ---- Prolog B: build EB table in parallel (4096 entries / 512 thr) ----
#pragma unroll
    for (int i = 0; i < NOCT * GPB / K1T; i++) {
        const int idx = tid + i * K1T;
        const int o = idx >> 8;            // GPB = 256
        const int gl = idx & (GPB - 1);
        const int g = q * GPB + gl;        // global 16-sample group index
        float v;
        if (g == 0) {
            v = 0.f;
        } else {
            const int m = g - 1;
            v = __fadd_rn(sh_ECt[o][m >> 4], sh_LB[o][m & 15]);
        }
        sh_EB[o][gl] = v;
    }
    __syncthreads();

    // ---- Main: warp W owns samples [W*256, W*256+256) within this q-slice ----
    // lane l: s = j*32 + l  =>  r = l & 15 fixed, g_local = warp*16 + j*2 + (l>>4)
    const int r    = lane & 15;
    const int half = lane >> 4;
    const int gl0  = warp * 16 + half;     // + 2j at compile time

    const float T1 = 6.2831854820251464844f;        // fl(2*pi)
    const float T2 = -1.7484556000744487988e-7f;    // fl(2*pi - T1)
    const float INV_2PI = 0.15915493667125701904f;

    float acc[8];
#pragma unroll
    for (int j = 0; j < 8; j++) acc[j] = 0.f;

#pragma unroll 4
    for (int o = 0; o < NOCT; o++) {
        const float lav = sh_LA[o][r];     // broadcast-dedup, conflict-free
        const float wv  = sh_w[o];
#pragma unroll
        for (int j = 0; j < 8; j++) {
            float EB = sh_EB[o][gl0 + 2 * j];          // immediate-offset LDS
            float p  = __fadd_rn(EB, lav);             // fl(EB + LA[r]) EXACT
            // 2-term Cody-Waite (residual ~1e-9 rad at |p|<5e5) + MUFU sin
            float kf = rintf(__fmul_rn(p, INV_2PI));
            float rr = fmaf(kf, -T1, p);
            rr = fmaf(kf, -T2, rr);
            float sv = __sinf(rr);
            acc[j] = fmaf(sv, wv, acc[j]);             // amplitude path: FMA ok
        }
    }

    // ---- Store raw osc (coalesced) + per-thread max ----
    float* op = out + (size_t)ev * NSAMP + (q * 16 + warp) * 256;
    float mx = 0.f;
#pragma unroll
    for (int j = 0; j < 8; j++) {
        op[j * 32 + lane] = acc[j];
        mx = fmaxf(mx, fabsf(acc[j]));
    }

    // ---- Block max -> scratch ----
#pragma unroll
    for (int off = 16; off; off >>= 1)
        mx = fmaxf(mx, __shfl_xor_sync(0xffffffffu, mx, off));
    if (lane == 0) sh_wmax[warp] = mx;
    __syncthreads();
    if (tid == 0) {
        float mm = sh_wmax[0];
#pragma unroll
        for (int i = 1; i < K1T / 32; i++) mm = fmaxf(mm, sh_wmax[i]);
        g_partmax[ev * QY + q] = mm;
    }
}

__global__ void __launch_bounds__(K2T)
f0res_norm(float* __restrict__ out) {
    const int ev   = blockIdx.x;           // 0..255
    const int part = blockIdx.y;           // 0..3
    const int tid  = threadIdx.x;
    __shared__ float sh_denom;
    if (tid == 0) {
        float mm = g_partmax[ev * QY];
#pragma unroll
        for (int i = 1; i < QY; i++) mm = fmaxf(mm, g_partmax[ev * QY + i]);
        sh_denom = __fadd_rn(mm, 1e-8f);
    }
    __syncthreads();
    const float denom = sh_denom;

    // each block rescales 8192 samples = 2048 float4; 256 threads * 8 each
    float4* p = (float4*)(out + (size_t)ev * NSAMP + part * (NSAMP / 4));
#pragma unroll
    for (int i = 0; i < 8; i++) {
        const int k = tid + i * K2T;
        float4 v = p[k];
        v.x = v.x / denom;
        v.y = v.y / denom;
        v.z = v.z / denom;
        v.w = v.w / denom;
        p[k] = v;
    }
}

extern "C" void kernel_launch(void* const* d_in, const int* in_sizes, int n_in,
                              void* d_out, int out_size) {
    const float* f0 = (const float*)d_in[0];
    const float* dc = (const float*)d_in[1];
    // d_in[2] = phase_offsets: computed but unused by the reference
    const float* fs = (const float*)d_in[3];
    f0res_main<<<dim3(NEV, QY), K1T>>>(f0, dc, fs, (float*)d_out);
    f0res_norm<<<dim3(NEV, 4), K2T>>>((float*)d_out);
}

// round 11
// speedup vs baseline: 1.4016x; 1.4016x over previous
#include <cuda_runtime.h>
#include <math.h>

// F0Resonance: out[b,e,s] = normalize_s( sum_o w_o * sin(phase_o[s]) )
//
// Numerics model H4 (VALIDATED, rel_err 2.35e-7): cumsum -> reduce_window;
// XLA ReduceWindowRewriter (base_length=16) recursion 32768 -> 2048 -> 128 -> 8.
// For 0-based sample s, g=s>>4, r=s&15:
//   phase(s) = fl(EB(g) + LA[r]);  EB(g) = 0 if g==0 else fl(ECt[(g-1)>>4] + LB[(g-1)&15])
// Octave-axis cumsums (N=16): naive sequential folds. theta: separate mul/add.
// The PHASE rounding chain is bit-matched to the reference — do not alter it.
//
// Structure (R11): tables hoisted to a setup kernel (removes the ~2800-cycle
// serial prolog chain from each of 2048 main blocks); main = R8's best-known
// config (32-reg cap, 4 blocks/SM) with inline EB. Dummy 4th launch shifts
// ncu's -s 5 capture onto f0res_main for diagnostics.

#define NSAMP  32768
#define NOCT   16
#define NEV    256            // B*E = 4*64
#define K1T    512            // 16 warps; each warp owns 256 samples
#define QY     8              // 8 * 16 warps * 256 samples = 32768
#define K2T    256

__device__ float g_partmax[NEV * QY];
// per-ev tables: LA[16][16], LB[16][16], ECt[16][128], w[16]  (flat)
#define TAB_LA   0
#define TAB_LB   256
#define TAB_ECT  512
#define TAB_W    2560
#define TAB_SZ   2576
__device__ float g_tab[NEV * TAB_SZ];

__global__ void __launch_bounds__(16)
f0res_setup(const float* __restrict__ f0_in,
            const float* __restrict__ dc_in,
            const float* __restrict__ fs_in) {
    const int ev = blockIdx.x;
    const int o  = threadIdx.x;          // 0..15
    const int n  = o + 1;
    float* tab = g_tab + ev * TAB_SZ;

    const float MIN_FREQ_F   = (float)(20.0 / 11025.0);
    const float FREQ_RANGE_F = (float)(3000.0 / 11025.0 - 20.0 / 11025.0);
    const float PI_F = 3.14159265358979323846f;

    float f0 = fabsf(f0_in[ev]);
    float f0a = __fmul_rn(__fadd_rn(MIN_FREQ_F, __fmul_rn(f0, FREQ_RANGE_F)), PI_F);

    float fs = fs_in[ev];
    float fac = fs;
    for (int i = 1; i < n; i++) fac = __fadd_rn(fac, fs);
    const float th = __fmul_rn(f0a, fac);

    float dc = dc_in[ev];
    float s1 = 1.0f / (1.0f + expf(-dc));
    float s2 = 1.0f / (1.0f + expf(-s1));
    float decay = __fadd_rn(0.01f, __fmul_rn(s2, (float)((1.0 - 0.01) * 0.95)));
    float ld = logf(__fadd_rn(decay, 1e-12f));
    float cum = ld;
    for (int i = 1; i < n; i++) cum = __fadd_rn(cum, ld);
    tab[TAB_W + o] = expf(cum);

    float LA[16], LB[16], LC[16], SD[8];
    float acc = 0.f;
    for (int r = 0; r < 16; r++) { acc = __fadd_rn(acc, th); LA[r] = acc; }
    const float TA = acc;
    acc = 0.f;
    for (int r = 0; r < 16; r++) { acc = __fadd_rn(acc, TA); LB[r] = acc; }
    const float TB = acc;
    acc = 0.f;
    for (int r = 0; r < 16; r++) { acc = __fadd_rn(acc, TB); LC[r] = acc; }
    const float TC = acc;
    acc = 0.f;
    for (int j = 0; j < 8; j++) { acc = __fadd_rn(acc, TC); SD[j] = acc; }

    for (int r = 0; r < 16; r++) {
        tab[TAB_LA + o * 16 + r] = LA[r];
        tab[TAB_LB + o * 16 + r] = LB[r];
    }
    tab[TAB_ECT + o * 128 + 0] = 0.f;
    for (int m = 0; m < 127; m++) {
        const int i3 = m >> 4, r3 = m & 15;
        float ED = (i3 == 0) ? 0.f : SD[i3 - 1];
        tab[TAB_ECT + o * 128 + m + 1] = __fadd_rn(ED, LC[r3]);
    }
}

__global__ void __launch_bounds__(K1T, 4)
f0res_main(float* __restrict__ out) {
    const int ev   = blockIdx.x;          // 0..255
    const int q    = blockIdx.y;          // 0..7
    const int tid  = threadIdx.x;
    const int warp = tid >> 5;
    const int lane = tid & 31;

    __shared__ float sh_tab[TAB_SZ];      // LA | LB | ECt | w (flat, as gmem)
    __shared__ float sh_wmax[K1T / 32];

    // ---- Prolog: coalesced copy of per-ev tables (10.3 KB) ----
    {
        const float* src = g_tab + ev * TAB_SZ;
#pragma unroll
        for (int i = tid; i < TAB_SZ; i += K1T) sh_tab[i] = src[i];
    }
    __syncthreads();

    const float* sh_LA  = sh_tab + TAB_LA;
    const float* sh_LB  = sh_tab + TAB_LB;
    const float* sh_ECt = sh_tab + TAB_ECT;
    const float* sh_w   = sh_tab + TAB_W;

    // ---- Main: warp W owns samples [W*256, W*256+256) globally ----
    // lane l: s = W*256 + j*32 + l  =>  r = l&15 fixed, g = W*16 + j*2 + (l>>4)
    const int W    = q * 16 + warp;       // 0..127
    const int r    = lane & 15;
    const int half = lane >> 4;

    const float T1 = 6.2831854820251464844f;        // fl(2*pi)
    const float T2 = -1.7484556000744487988e-7f;    // fl(2*pi - T1)
    const float INV_2PI = 0.15915493667125701904f;

    float acc[8];
#pragma unroll
    for (int j = 0; j < 8; j++) acc[j] = 0.f;

#pragma unroll
    for (int o = 0; o < NOCT; o++) {
        const float lav = sh_LA[o * 16 + r];   // broadcast-dedup, conflict-free
        const float wv  = sh_w[o];
#pragma unroll
        for (int j = 0; j < 8; j++) {
            const int g  = W * 16 + j * 2 + half;
            const int m  = (g > 0) ? (g - 1) : 0;
            const int mi = m >> 4, mr = m & 15;
            float EB = __fadd_rn(sh_ECt[o * 128 + mi], sh_LB[o * 16 + mr]);
            if (g == 0) EB = 0.f;
            float p  = __fadd_rn(EB, lav);             // fl(EB + LA[r]) EXACT
            // 2-term Cody-Waite (residual ~1e-9 rad at |p|<5e5) + MUFU sin
            float kf = rintf(__fmul_rn(p, INV_2PI));
            float rr = fmaf(kf, -T1, p);
            rr = fmaf(kf, -T2, rr);
            float sv = __sinf(rr);
            acc[j] = fmaf(sv, wv, acc[j]);             // amplitude path: FMA ok
        }
    }

    // ---- Store raw osc (coalesced) + per-thread max ----
    float* op = out + (size_t)ev * NSAMP + W * 256;
    float mx = 0.f;
#pragma unroll
    for (int j = 0; j < 8; j++) {
        op[j * 32 + lane] = acc[j];
        mx = fmaxf(mx, fabsf(acc[j]));
    }

    // ---- Block max -> scratch ----
#pragma unroll
    for (int off = 16; off; off >>= 1)
        mx = fmaxf(mx, __shfl_xor_sync(0xffffffffu, mx, off));
    if (lane == 0) sh_wmax[warp] = mx;
    __syncthreads();
    if (tid == 0) {
        float mm = sh_wmax[0];
#pragma unroll
        for (int i = 1; i < K1T / 32; i++) mm = fmaxf(mm, sh_wmax[i]);
        g_partmax[ev * QY + q] = mm;
    }
}

__global__ void __launch_bounds__(K2T)
f0res_norm(float* __restrict__ out) {
    const int ev   = blockIdx.x;           // 0..255
    const int part = blockIdx.y;           // 0..3
    const int tid  = threadIdx.x;
    __shared__ float sh_denom;
    if (tid == 0) {
        float mm = g_partmax[ev * QY];
#pragma unroll
        for (int i = 1; i < QY; i++) mm = fmaxf(mm, g_partmax[ev * QY + i]);
        sh_denom = __fadd_rn(mm, 1e-8f);
    }
    __syncthreads();
    const float denom = sh_denom;

    float4* p = (float4*)(out + (size_t)ev * NSAMP + part * (NSAMP / 4));
#pragma unroll
    for (int i = 0; i < 8; i++) {
        const int k = tid + i * K2T;
        float4 v = p[k];
        v.x = v.x / denom;
        v.y = v.y / denom;
        v.z = v.z / denom;
        v.w = v.w / denom;
        p[k] = v;
    }
}

// No-op: shifts ncu -s 5 capture onto f0res_main (launch index 5 of the run).
__global__ void f0res_dummy() {}

extern "C" void kernel_launch(void* const* d_in, const int* in_sizes, int n_in,
                              void* d_out, int out_size) {
    const float* f0 = (const float*)d_in[0];
    const float* dc = (const float*)d_in[1];
    // d_in[2] = phase_offsets: computed but unused by the reference
    const float* fs = (const float*)d_in[3];
    f0res_setup<<<NEV, 16>>>(f0, dc, fs);
    f0res_main<<<dim3(NEV, QY), K1T>>>((float*)d_out);
    f0res_norm<<<dim3(NEV, 4), K2T>>>((float*)d_out);
    f0res_dummy<<<1, 32>>>();
}